// round 17
// baseline (speedup 1.0000x reference)
#include <cuda_runtime.h>
#include <cuda_fp16.h>
#include <stdint.h>

// OpticalConvolution: 3x3 conv pad1 stride1, B=16 Cin=128 H=W=56 Cout=256, fp32.
//
// Round 17: R16 single-GEMM fp16 HMMA + register-prefetch B pipeline:
//  - input packed as padded NHWC-pair [b][py][px][jp(64)] u32 planes, so each
//    thread's stage-B slice is 32 contiguous bytes: 2x LDG.128 + 2x STS.128,
//    static offsets, conflict-free vs SW128.
//  - B(s+3) is LDG'd into registers at stage s and STS'd at stage s+1 into
//    buf[(s+3)%3]: the ~300cyc L2 latency is covered by a full compute stage.
// M128xN64 CTA, 8 warps 4Mx2N 32x32 tiles, triple-buffered 72KB, 2 CTAs/SM.

#define CIN   128
#define COUT  256
#define HH    56
#define WW    56
#define HP    58                   // padded spatial dim
#define HW    (HH * WW)
#define KTOT  1152
#define NSTAGES 18

#define A_SZ 16384                 // 128 rows x 128B (fp16 weights)
#define B_SZ 8192                  // 64 rows x 128B (fp16 input)
#define A_HI 0
#define B_HI (A_SZ)
#define BUFSZ (A_SZ + B_SZ)              // 24576
#define SMEM_TOTAL (3 * BUFSZ)           // 73728

#define SWZ(x) ((x) ^ (((x) >> 3) & 0x70))

__device__ __align__(16) uint8_t W_img[2][NSTAGES][A_SZ];   // fp16, k'-order, swizzled
// padded NHWC-pair: [b][py(58)][px(58)][jp(64)], u32 = h(2jp+1)<<16 | h(2jp)
__device__ __align__(16) uint32_t Xp2[16 * HP * HP * 64];

__device__ __forceinline__ uint32_t s2u(const void* p) {
    uint32_t a;
    asm("{.reg .u64 t; cvta.to.shared.u64 t, %1; cvt.u32.u64 %0, t;}" : "=r"(a) : "l"(p));
    return a;
}

__device__ __forceinline__ void mma_f16(float* d, const uint32_t* a, const uint32_t* b) {
    asm volatile(
        "mma.sync.aligned.m16n8k16.row.col.f32.f16.f16.f32 "
        "{%0,%1,%2,%3}, {%4,%5,%6,%7}, {%8,%9}, {%0,%1,%2,%3};"
        : "+f"(d[0]), "+f"(d[1]), "+f"(d[2]), "+f"(d[3])
        : "r"(a[0]), "r"(a[1]), "r"(a[2]), "r"(a[3]), "r"(b[0]), "r"(b[1]));
}

#define LDSM4(r, a) \
    asm volatile("ldmatrix.sync.aligned.m8n8.x4.shared.b16 {%0,%1,%2,%3}, [%4];" \
                 : "=r"((r)[0]), "=r"((r)[1]), "=r"((r)[2]), "=r"((r)[3]) : "r"(a))

#define STS128(addr, v) \
    asm volatile("st.shared.v4.b32 [%0], {%1,%2,%3,%4};" \
                 :: "r"(addr), "r"((v).x), "r"((v).y), "r"((v).z), "r"((v).w) : "memory")

// ---------------- prep 1: NCHW fp32 -> padded NHWC-pair u32 ----------------
__global__ void pack_kernel(const float* __restrict__ in)
{
    const int py = blockIdx.x;          // 0..57
    const int b  = blockIdx.y;
    const int t  = threadIdx.x;         // 256
    uint32_t* dst = Xp2 + (size_t)(b * HP + py) * (HP * 64);

    if (py == 0 || py == HP - 1) {
        for (int i = t; i < HP * 64; i += 256) dst[i] = 0;
        return;
    }

    __shared__ uint32_t sp[64 * 59];    // [jp][x], stride 59 (odd -> conflict-free)
    const float* src = in + (size_t)b * CIN * HW + (py - 1) * WW;
    for (int i = t; i < 64 * 56; i += 256) {
        int jp = i / 56, x = i - jp * 56;
        float v0 = src[(size_t)(2 * jp) * HW + x];
        float v1 = src[(size_t)(2 * jp + 1) * HW + x];
        uint32_t h0 = __half_as_ushort(__float2half_rn(v0));
        uint32_t h1 = __half_as_ushort(__float2half_rn(v1));
        sp[jp * 59 + x] = (h1 << 16) | h0;
    }
    __syncthreads();
    for (int i = t; i < HP * 64; i += 256) {
        int px = i >> 6, jp = i & 63;
        uint32_t v = 0;
        if (px >= 1 && px <= 56) v = sp[jp * 59 + px - 1];
        dst[(size_t)px * 64 + jp] = v;  // coalesced (jp fast)
    }
}

// ---------------- prep 2: fp16 weights, k'-order, swizzled images ----------------
__global__ void wprep_kernel(const float* __restrict__ wt)
{
    const int tid = blockIdx.x * blockDim.x + threadIdx.x;
    const int nth = gridDim.x * blockDim.x;
    const int WTOT = 2 * NSTAGES * 128 * 32;
    for (int i = tid; i < WTOT; i += nth) {
        int cb  = i / (NSTAGES * 128 * 32);
        int rem = i - cb * (NSTAGES * 128 * 32);
        int s   = rem >> 12;
        int row = (rem >> 5) & 127;
        int j   = rem & 31;
        int r   = s >> 1;                  // filter tap 0..8
        int ci0 = (s & 1) * 64 + 2 * j;    // channel pair
        const float* p = wt + (size_t)(cb * 128 + row) * KTOT;
        uint32_t h0 = __half_as_ushort(__float2half_rn(p[ci0 * 9 + r]));
        uint32_t h1 = __half_as_ushort(__float2half_rn(p[(ci0 + 1) * 9 + r]));
        uint32_t off = SWZ((uint32_t)row * 128 + j * 4);
        *(uint32_t*)&W_img[cb][s][off] = (h1 << 16) | h0;   // even k' in low half
    }
}

// ---------------- main GEMM kernel: M=128 x N=64 per CTA ----------------
__global__ __launch_bounds__(256, 2)
void conv_mma(const float* __restrict__ bias, float* __restrict__ out)
{
    extern __shared__ __align__(1024) char smem[];
    const uint32_t sb = s2u(smem);
    const int t = threadIdx.x;
    const int wid = t >> 5;
    const int lane = t & 31;

    const int tileId = blockIdx.x;          // 0..48
    const int ty = tileId / 7, tx = tileId % 7;
    const int y0 = ty * 8, x0 = tx * 8;
    const int cb = blockIdx.y;
    const int co0 = cb * 128;
    const int bz = blockIdx.z;

    // ---- B-staging constants: thread <-> n-row (64), quarter <-> 8 jp ----
    const int nB = t & 63;
    const int q4 = t >> 6;                  // 0..3
    const int yy = nB >> 3, xx = nB & 7;
    // pixel base (padded coords: py = y0+yy+ky for tap ky since pad shift +1)
    const uint32_t* pixbase = Xp2
        + ((size_t)(bz * HP + y0 + yy) * HP + (x0 + xx)) * 64 + q4 * 8;
    const uint32_t swz0 = SWZ((uint32_t)nB * 128 + (uint32_t)q4 * 32);
    const uint32_t swz1 = SWZ((uint32_t)nB * 128 + (uint32_t)q4 * 32 + 16);

    // ---- warp tiling: 4 (M) x 2 (N); warp tile 32 x 32 ----
    const int mrow = (wid & 3) * 32;
    const int ncol = (wid >> 2) * 32;
    const int g = lane >> 2;
    const int c = lane & 3;

    // ---- ldmatrix per-lane address components ----
    const int arow = lane & 15;
    const uint32_t akoff = (uint32_t)(lane >> 4) << 4;
    const uint32_t xrA = (uint32_t)(arow & 7) << 4;
    uint32_t rbA[2];
    rbA[0] = (uint32_t)(mrow + arow) * 128;
    rbA[1] = (uint32_t)(mrow + 16 + arow) * 128;
    const int brow = (lane & 7) | ((lane >> 4) << 3);
    const uint32_t bkoff = (uint32_t)((lane >> 3) & 1) << 4;
    const uint32_t xrB = (uint32_t)(brow & 7) << 4;
    uint32_t rbB[2];
    rbB[0] = (uint32_t)(ncol + brow) * 128;
    rbB[1] = (uint32_t)(ncol + 16 + brow) * 128;

    float acc[2][4][4];
    #pragma unroll
    for (int mt = 0; mt < 2; mt++)
        #pragma unroll
        for (int nt = 0; nt < 4; nt++)
            #pragma unroll
            for (int r = 0; r < 4; r++) acc[mt][nt][r] = 0.0f;

    uint4 pend0, pend1;                     // registered B slice (32B)

    auto stageA = [&](int s, int buf) {
        const uint8_t* ws = &W_img[cb][s][0];
        uint32_t dst = sb + buf * BUFSZ + A_HI;
        #pragma unroll
        for (int it = 0; it < 4; it++) {
            uint32_t off = it * 4096 + t * 16;
            asm volatile("cp.async.cg.shared.global [%0], [%1], 16;"
                         :: "r"(dst + off), "l"(ws + off) : "memory");
        }
    };
    auto ldgB = [&](int s) {
        int r  = s >> 1;
        int ky = (r >= 6) ? 2 : (r >= 3 ? 1 : 0);
        int kx = r - ky * 3;
        const uint4* p = (const uint4*)(pixbase + (ky * HP + kx) * 64 + (s & 1) * 32);
        pend0 = p[0];
        pend1 = p[1];
    };
    auto stsB = [&](int buf) {
        uint32_t d = sb + buf * BUFSZ + B_HI;
        STS128(d + swz0, pend0);
        STS128(d + swz1, pend1);
    };

    // ---- prologue ----
    stageA(0, 0);
    asm volatile("cp.async.commit_group;" ::: "memory");   // G0 = A(0)
    stageA(1, 1);
    asm volatile("cp.async.commit_group;" ::: "memory");   // G1 = A(1)
    ldgB(0); stsB(0);
    ldgB(1); stsB(1);
    ldgB(2);                                               // pend holds B(2)

    for (int s = 0; s < NSTAGES; s++) {
        if (s < NSTAGES - 1)
            asm volatile("cp.async.wait_group 1;" ::: "memory");   // completes G(s)=A(s)
        else
            asm volatile("cp.async.wait_group 0;" ::: "memory");
        __syncthreads();

        const uint32_t cu = sb + (uint32_t)(s % 3) * BUFSZ;
        #pragma unroll
        for (int q = 0; q < 4; q++) {
            const uint32_t kA = (uint32_t)(q * 32) + akoff;
            const uint32_t kB = (uint32_t)(q * 32) + bkoff;
            uint32_t bh[2][4], ah[2][4];
            #pragma unroll
            for (int np = 0; np < 2; np++)
                LDSM4(bh[np], cu + rbB[np] + (kB ^ xrB) + B_HI);
            #pragma unroll
            for (int mt = 0; mt < 2; mt++)
                LDSM4(ah[mt], cu + rbA[mt] + (kA ^ xrA) + A_HI);
            #pragma unroll
            for (int mt = 0; mt < 2; mt++)
                #pragma unroll
                for (int np = 0; np < 2; np++) {
                    mma_f16(acc[mt][2 * np],     ah[mt], &bh[np][0]);
                    mma_f16(acc[mt][2 * np + 1], ah[mt], &bh[np][2]);
                }
        }

        // stage s+2 into buf (s+2)%3: STS the registered B, async-copy A
        if (s + 2 < NSTAGES) {
            stsB((s + 2) % 3);
            stageA(s + 2, (s + 2) % 3);
            asm volatile("cp.async.commit_group;" ::: "memory");   // G(s+2)
        }
        // prefetch B for s+3 into registers (consumed by stsB at stage s+1)
        if (s + 3 < NSTAGES)
            ldgB(s + 3);
    }

    // ---- epilogue: bias + direct float2 stores ----
    #pragma unroll
    for (int mt = 0; mt < 2; mt++) {
        int coA = co0 + mrow + mt * 16 + g;
        int coB = coA + 8;
        float bvA = __ldg(&bias[coA]);
        float bvB = __ldg(&bias[coB]);
        #pragma unroll
        for (int nt = 0; nt < 4; nt++) {
            int n0 = ncol + nt * 8 + c * 2;       // 0..63
            int yq = n0 >> 3, xq = n0 & 7;
            float* gA = out + (((size_t)bz * COUT + coA) * HH + (y0 + yq)) * WW + x0 + xq;
            float* gB = out + (((size_t)bz * COUT + coB) * HH + (y0 + yq)) * WW + x0 + xq;
            *(float2*)gA = make_float2(acc[mt][nt][0] + bvA, acc[mt][nt][1] + bvA);
            *(float2*)gB = make_float2(acc[mt][nt][2] + bvB, acc[mt][nt][3] + bvB);
        }
    }
}

extern "C" void kernel_launch(void* const* d_in, const int* in_sizes, int n_in,
                              void* d_out, int out_size)
{
    const float* tensor  = (const float*)d_in[0];   // [16,128,56,56]
    const float* weights = (const float*)d_in[1];   // [256,128,3,3]
    const float* bias    = (const float*)d_in[2];   // [256]
    float* out = (float*)d_out;                     // [16,256,56,56]

    pack_kernel<<<dim3(HP, 16), 256>>>(tensor);
    wprep_kernel<<<288, 256>>>(weights);

    cudaFuncSetAttribute(conv_mma,
                         cudaFuncAttributeMaxDynamicSharedMemorySize, SMEM_TOTAL);
    dim3 grid(49, 2, 16);
    conv_mma<<<grid, 256, SMEM_TOTAL>>>(bias, out);
}